// round 1
// baseline (speedup 1.0000x reference)
#include <cuda_runtime.h>
#include <cuda_bf16.h>

#define NR 8192
#define IN_SZ 512
#define FEAT 128
#define NOUT 512

// Scratch (static device globals — allocation-free per harness rules)
__device__ float g_q [NR * FEAT];
__device__ float g_k [NR * FEAT];
__device__ float g_v1[NR * NOUT];
__device__ float g_v2[NR * NOUT];
__device__ float g_S [(size_t)NR * NR];     // 256 MiB: logits -> probs (in place)
__device__ float g_Pp[NR * NOUT];           // prefix sum of v2
__device__ float g_Qp[NR * NOUT];           // prefix sum of j*v2

// ---------------------------------------------------------------------------
// Generic tiled SGEMM: C[M,N] = A[M,K] @ B
//   BT=true : B is [N,K] row-major (i.e. C = A @ B^T)
//   BT=false: B is [K,N] row-major
//   EPI=true: fused final epilogue: C = 0.5*acc + 0.5*time_term  (N == NOUT)
// Tile 128x128x8, 256 threads, 8x8 per thread. M,N multiples of 128; K of 8.
// ---------------------------------------------------------------------------
template <bool BT, bool EPI>
__global__ void __launch_bounds__(256)
sgemm_kernel(const float* __restrict__ A, const float* __restrict__ B,
             float* __restrict__ C, int M, int N, int K,
             const float* __restrict__ Pp, const float* __restrict__ Qp)
{
    __shared__ float As[8][128];
    __shared__ float Bs[8][128];

    const int tid  = threadIdx.x;
    const int bx   = blockIdx.x;   // N tile
    const int by   = blockIdx.y;   // M tile
    const int row0 = (tid >> 4) * 8;   // 0..120
    const int col0 = (tid & 15) * 8;   // 0..120

    const int ar = tid >> 1;           // 0..127
    const int ac = (tid & 1) * 4;      // 0 or 4

    const float* Aload = A + ((size_t)by * 128 + ar) * K + ac;

    float acc[8][8];
#pragma unroll
    for (int i = 0; i < 8; ++i)
#pragma unroll
        for (int j = 0; j < 8; ++j) acc[i][j] = 0.0f;

    for (int k0 = 0; k0 < K; k0 += 8) {
        // --- load A tile [128 x 8], store transposed As[k][m]
        float4 av = *(const float4*)(Aload + k0);
        As[ac + 0][ar] = av.x;
        As[ac + 1][ar] = av.y;
        As[ac + 2][ar] = av.z;
        As[ac + 3][ar] = av.w;

        // --- load B tile
        if (BT) {
            // B[N,K]: rows n = bx*128 + ar, cols k0+ac..k0+ac+3 -> Bs[k][n]
            float4 bv = *(const float4*)(B + ((size_t)bx * 128 + ar) * K + k0 + ac);
            Bs[ac + 0][ar] = bv.x;
            Bs[ac + 1][ar] = bv.y;
            Bs[ac + 2][ar] = bv.z;
            Bs[ac + 3][ar] = bv.w;
        } else {
            // B[K,N]: rows k0+br (br=0..7), cols bx*128 + bc..bc+3
            int br = tid >> 5;           // 0..7
            int bc = (tid & 31) * 4;     // 0..124
            float4 bv = *(const float4*)(B + (size_t)(k0 + br) * N + bx * 128 + bc);
            *(float4*)&Bs[br][bc] = bv;
        }
        __syncthreads();

#pragma unroll
        for (int kk = 0; kk < 8; ++kk) {
            float a[8], b[8];
            *(float4*)(a)     = *(const float4*)&As[kk][row0];
            *(float4*)(a + 4) = *(const float4*)&As[kk][row0 + 4];
            *(float4*)(b)     = *(const float4*)&Bs[kk][col0];
            *(float4*)(b + 4) = *(const float4*)&Bs[kk][col0 + 4];
#pragma unroll
            for (int i = 0; i < 8; ++i)
#pragma unroll
                for (int j = 0; j < 8; ++j) acc[i][j] += a[i] * b[j];
        }
        __syncthreads();
    }

    const size_t grow = (size_t)by * 128 + row0;
    const int    gcol = bx * 128 + col0;

    if (!EPI) {
#pragma unroll
        for (int i = 0; i < 8; ++i) {
            *(float4*)&C[(grow + i) * N + gcol]     =
                make_float4(acc[i][0], acc[i][1], acc[i][2], acc[i][3]);
            *(float4*)&C[(grow + i) * N + gcol + 4] =
                make_float4(acc[i][4], acc[i][5], acc[i][6], acc[i][7]);
        }
    } else {
        // out[i,c] = 0.5*attn + 0.5*(G_time @ v2)[i,c] via prefix sums
        // numer_i = (n+i)*Ptot - Qtot - 2*i*P_i + 2*Q_i
        // rowsum_i = n^2 - (i(i+1)/2 + (n-1-i)(n-i)/2)
#pragma unroll
        for (int i = 0; i < 8; ++i) {
            const long long ir = (long long)(grow + i);
            const long long s1 = ir * (ir + 1) / 2;
            const long long s2 = (long long)(NR - 1 - ir) * (NR - ir) / 2;
            const float inv_rs = 1.0f / (float)((long long)NR * NR - s1 - s2);
            const float fi = (float)ir;
#pragma unroll
            for (int j = 0; j < 8; ++j) {
                const int c  = gcol + j;
                const float Pt = Pp[(size_t)(NR - 1) * NOUT + c];
                const float Qt = Qp[(size_t)(NR - 1) * NOUT + c];
                const float Pi = Pp[(size_t)ir * NOUT + c];
                const float Qi = Qp[(size_t)ir * NOUT + c];
                const float numer = ((float)NR + fi) * Pt - Qt - 2.0f * fi * Pi + 2.0f * Qi;
                C[(size_t)ir * NOUT + c] = 0.5f * acc[i][j] + 0.5f * numer * inv_rs;
            }
        }
    }
}

// ---------------------------------------------------------------------------
// Row softmax in place: one block per row, row (8192 floats = 32KB) in smem
// ---------------------------------------------------------------------------
__global__ void __launch_bounds__(256)
softmax_rows_kernel(float* __restrict__ S)
{
    __shared__ float row[NR];
    __shared__ float red[256];
    const int tid = threadIdx.x;
    float* Sr = S + (size_t)blockIdx.x * NR;

    float m = -1e30f;
    for (int t = tid; t < NR; t += 256) {
        float v = Sr[t];
        row[t] = v;
        m = fmaxf(m, v);
    }
    red[tid] = m;
    __syncthreads();
    for (int off = 128; off > 0; off >>= 1) {
        if (tid < off) red[tid] = fmaxf(red[tid], red[tid + off]);
        __syncthreads();
    }
    m = red[0];
    __syncthreads();

    float s = 0.0f;
    for (int t = tid; t < NR; t += 256) {
        float e = __expf(row[t] - m);
        row[t] = e;
        s += e;
    }
    red[tid] = s;
    __syncthreads();
    for (int off = 128; off > 0; off >>= 1) {
        if (tid < off) red[tid] += red[tid + off];
        __syncthreads();
    }
    const float inv = 1.0f / red[0];

    for (int t = tid; t < NR; t += 256)
        Sr[t] = row[t] * inv;
}

// ---------------------------------------------------------------------------
// Time-path column scan: per column c, inclusive prefix sums of v2 and j*v2.
// fp64 accumulation (cheap: 4M elements), stored as fp32.
// ---------------------------------------------------------------------------
__global__ void __launch_bounds__(256)
time_scan_kernel(const float* __restrict__ v2,
                 float* __restrict__ Pp, float* __restrict__ Qp)
{
    __shared__ double sp[256];
    __shared__ double sq[256];
    __shared__ double carry[2];
    const int c   = blockIdx.x;
    const int tid = threadIdx.x;

    if (tid == 0) { carry[0] = 0.0; carry[1] = 0.0; }
    __syncthreads();

    for (int chunk = 0; chunk < NR / 256; ++chunk) {
        const int row = chunk * 256 + tid;
        const double v = (double)v2[(size_t)row * NOUT + c];
        sp[tid] = v;
        sq[tid] = (double)row * v;
        __syncthreads();
        for (int off = 1; off < 256; off <<= 1) {
            double ap = 0.0, aq = 0.0;
            if (tid >= off) { ap = sp[tid - off]; aq = sq[tid - off]; }
            __syncthreads();
            if (tid >= off) { sp[tid] += ap; sq[tid] += aq; }
            __syncthreads();
        }
        const double p = sp[tid] + carry[0];
        const double q = sq[tid] + carry[1];
        Pp[(size_t)row * NOUT + c] = (float)p;
        Qp[(size_t)row * NOUT + c] = (float)q;
        __syncthreads();
        if (tid == 255) { carry[0] = p; carry[1] = q; }
        __syncthreads();
    }
}

// ---------------------------------------------------------------------------
extern "C" void kernel_launch(void* const* d_in, const int* in_sizes, int n_in,
                              void* d_out, int out_size)
{
    const float* x  = (const float*)d_in[0];   // [8192, 512]
    const float* W0 = (const float*)d_in[1];   // [128, 512]
    const float* W1 = (const float*)d_in[2];   // [128, 512]
    const float* w  = (const float*)d_in[3];   // [512, 512]
    const float* wt = (const float*)d_in[4];   // [512, 512]
    float* out = (float*)d_out;                // [8192, 512]

    float *q, *k, *v1, *v2, *S, *Pp, *Qp;
    cudaGetSymbolAddress((void**)&q,  g_q);
    cudaGetSymbolAddress((void**)&k,  g_k);
    cudaGetSymbolAddress((void**)&v1, g_v1);
    cudaGetSymbolAddress((void**)&v2, g_v2);
    cudaGetSymbolAddress((void**)&S,  g_S);
    cudaGetSymbolAddress((void**)&Pp, g_Pp);
    cudaGetSymbolAddress((void**)&Qp, g_Qp);

    // q = x @ W0^T, k = x @ W1^T   [8192,128]
    sgemm_kernel<true,  false><<<dim3(FEAT / 128, NR / 128), 256>>>(
        x, W0, q, NR, FEAT, IN_SZ, nullptr, nullptr);
    sgemm_kernel<true,  false><<<dim3(FEAT / 128, NR / 128), 256>>>(
        x, W1, k, NR, FEAT, IN_SZ, nullptr, nullptr);

    // v1 = x @ weight, v2 = x @ weight_time   [8192,512]
    sgemm_kernel<false, false><<<dim3(NOUT / 128, NR / 128), 256>>>(
        x, w,  v1, NR, NOUT, IN_SZ, nullptr, nullptr);
    sgemm_kernel<false, false><<<dim3(NOUT / 128, NR / 128), 256>>>(
        x, wt, v2, NR, NOUT, IN_SZ, nullptr, nullptr);

    // time-path prefix sums over v2
    time_scan_kernel<<<NOUT, 256>>>(v2, Pp, Qp);

    // S = q @ k^T   [8192,8192]
    sgemm_kernel<true,  false><<<dim3(NR / 128, NR / 128), 256>>>(
        q, k, S, NR, NR, FEAT, nullptr, nullptr);

    // P = softmax(S) rows, in place
    softmax_rows_kernel<<<NR, 256>>>(S);

    // out = 0.5 * (P @ v1) + 0.5 * time_term   (fused epilogue)
    sgemm_kernel<false, true><<<dim3(NOUT / 128, NR / 128), 256>>>(
        S, v1, out, NR, NOUT, NR, Pp, Qp);
}

// round 3
// speedup vs baseline: 1.8262x; 1.8262x over previous
#include <cuda_runtime.h>
#include <cuda_fp16.h>
#include <cstdint>

#define NR 8192
#define INSZ 512
#define FEAT 128
#define NOUT 512

typedef __half h16;

// ---------------------------------------------------------------------------
// Scratch (static device globals — allocation-free per harness rules)
// ---------------------------------------------------------------------------
__device__ __align__(16) h16 g_xh[NR * INSZ], g_xl[NR * INSZ];
__device__ __align__(16) h16 g_W0h[FEAT * INSZ], g_W0l[FEAT * INSZ];
__device__ __align__(16) h16 g_W1h[FEAT * INSZ], g_W1l[FEAT * INSZ];
__device__ __align__(16) h16 g_wTh[NOUT * INSZ], g_wTl[NOUT * INSZ];
__device__ __align__(16) h16 g_wtTh[NOUT * INSZ], g_wtTl[NOUT * INSZ];
__device__ __align__(16) h16 g_qh[NR * FEAT], g_ql[NR * FEAT];
__device__ __align__(16) h16 g_kh[NR * FEAT], g_kl[NR * FEAT];
__device__ __align__(16) h16 g_v1Th[(size_t)NOUT * NR], g_v1Tl[(size_t)NOUT * NR];
__device__ __align__(16) float g_v2T[(size_t)NOUT * NR];
__device__ __align__(16) float g_S[(size_t)NR * NR];  // fp32 logits -> in-place h16 hi|lo per row
__device__ __align__(16) float g_Pp[(size_t)NOUT * NR];
__device__ __align__(16) float g_Qp[(size_t)NOUT * NR];

// ---------------------------------------------------------------------------
// PTX helpers (base sm_103 target: cp.async / ldmatrix / mma.sync only)
// ---------------------------------------------------------------------------
__device__ __forceinline__ uint32_t smem_to_u32(const void* p) {
    uint32_t a;
    asm("{ .reg .u64 t; cvta.to.shared.u64 t, %1; cvt.u32.u64 %0, t; }" : "=r"(a) : "l"(p));
    return a;
}
__device__ __forceinline__ void cp16(uint32_t s, const void* g) {
    asm volatile("cp.async.cg.shared.global [%0], [%1], 16;" :: "r"(s), "l"(g));
}
__device__ __forceinline__ void cp_commit() { asm volatile("cp.async.commit_group;"); }
__device__ __forceinline__ void cp_wait2()  { asm volatile("cp.async.wait_group 2;"); }

__device__ __forceinline__ void ldm_x4(uint32_t& r0, uint32_t& r1, uint32_t& r2, uint32_t& r3,
                                       uint32_t addr) {
    asm volatile("ldmatrix.sync.aligned.m8n8.x4.shared.b16 {%0,%1,%2,%3}, [%4];"
                 : "=r"(r0), "=r"(r1), "=r"(r2), "=r"(r3) : "r"(addr));
}
__device__ __forceinline__ void mma16816(float* c, const uint32_t* a, const uint32_t* b) {
    asm volatile(
        "mma.sync.aligned.m16n8k16.row.col.f32.f16.f16.f32 "
        "{%0,%1,%2,%3}, {%4,%5,%6,%7}, {%8,%9}, {%0,%1,%2,%3};"
        : "+f"(c[0]), "+f"(c[1]), "+f"(c[2]), "+f"(c[3])
        : "r"(a[0]), "r"(a[1]), "r"(a[2]), "r"(a[3]), "r"(b[0]), "r"(b[1]));
}

__device__ __forceinline__ void split2h(float v, h16& h, h16& l) {
    h = __float2half_rn(v);
    l = __float2half_rn(v - __half2float(h));
}

// ---------------------------------------------------------------------------
// HMMA GEMM: C[M,N] = A[M,K] @ B[N,K]^T, A/B as fp16 (hi,lo), 3-product emu.
// CTA tile 128x128x32; 8 warps (2M x 4N), warp tile 64x32; 3-stage cp.async.
// EPI: 0 fp32 store; 1 h16 hi/lo pair store; 2 fused final epilogue.
// ---------------------------------------------------------------------------
#define STG   40960                 // 4 operands x 128 rows x 80B
#define OPA_H 0
#define OPA_L 10240
#define OPB_H 20480
#define OPB_L 30720
#define SMEM_DYN (3 * STG)

template <int EPI>
__global__ void __launch_bounds__(256, 1)
gemmH(const h16* __restrict__ Ah, const h16* __restrict__ Al, size_t lda,
      const h16* __restrict__ Bh, const h16* __restrict__ Bl, size_t ldb,
      float* __restrict__ Cf, h16* __restrict__ Ch, h16* __restrict__ Cl,
      size_t ldc, int K,
      const float* __restrict__ Pp, const float* __restrict__ Qp)
{
    extern __shared__ char smem[];
    const uint32_t sb = smem_to_u32(smem);
    const int tid  = threadIdx.x;
    const int lane = tid & 31, wid = tid >> 5;
    const int wm   = wid >> 2, wn = wid & 3;
    const int m0   = blockIdx.y * 128;
    const int n0   = blockIdx.x * 128;

    const int lrow = tid >> 1;          // 0..127
    const int lc0  = (tid & 1) * 2;     // 16B chunk 0 or 2

    float acc[4][4][4];
#pragma unroll
    for (int i = 0; i < 4; ++i)
#pragma unroll
        for (int j = 0; j < 4; ++j)
#pragma unroll
            for (int e = 0; e < 4; ++e) acc[i][j][e] = 0.0f;

    auto load_stage = [&](int buf, int chunk) {
        const size_t k0 = (size_t)chunk * 32;
        const uint32_t s0 = sb + buf * STG;
        const uint32_t so = (uint32_t)lrow * 80 + lc0 * 16;
        const h16* pAh = Ah + (size_t)(m0 + lrow) * lda + k0 + lc0 * 8;
        const h16* pAl = Al + (size_t)(m0 + lrow) * lda + k0 + lc0 * 8;
        const h16* pBh = Bh + (size_t)(n0 + lrow) * ldb + k0 + lc0 * 8;
        const h16* pBl = Bl + (size_t)(n0 + lrow) * ldb + k0 + lc0 * 8;
        cp16(s0 + OPA_H + so, pAh);      cp16(s0 + OPA_H + so + 16, pAh + 8);
        cp16(s0 + OPA_L + so, pAl);      cp16(s0 + OPA_L + so + 16, pAl + 8);
        cp16(s0 + OPB_H + so, pBh);      cp16(s0 + OPB_H + so + 16, pBh + 8);
        cp16(s0 + OPB_L + so, pBl);      cp16(s0 + OPB_L + so + 16, pBl + 8);
    };

    const int rsel = (lane & 7) + ((lane >> 3) & 1) * 8;
    const uint32_t koff_lane = ((lane >> 4) & 1) * 16;

    auto comp_chunk = [&](int buf) {
        const uint32_t base = sb + buf * STG;
#pragma unroll
        for (int sk = 0; sk < 2; ++sk) {
            uint32_t ah[4][4], al[4][4], bh[4][2], bl[4][2];
            const uint32_t koff = sk * 32 + koff_lane;
#pragma unroll
            for (int mt = 0; mt < 4; ++mt) {
                const uint32_t ra =
                    base + OPA_H + (uint32_t)(wm * 64 + mt * 16 + rsel) * 80 + koff;
                ldm_x4(ah[mt][0], ah[mt][1], ah[mt][2], ah[mt][3], ra);
                ldm_x4(al[mt][0], al[mt][1], al[mt][2], al[mt][3], ra + (OPA_L - OPA_H));
            }
#pragma unroll
            for (int nt2 = 0; nt2 < 2; ++nt2) {
                const uint32_t rb =
                    base + OPB_H + (uint32_t)(wn * 32 + nt2 * 16 + rsel) * 80 + koff;
                uint32_t t0, t1, t2, t3;
                ldm_x4(t0, t1, t2, t3, rb);
                bh[nt2 * 2][0] = t0; bh[nt2 * 2][1] = t2;
                bh[nt2 * 2 + 1][0] = t1; bh[nt2 * 2 + 1][1] = t3;
                ldm_x4(t0, t1, t2, t3, rb + (OPB_L - OPB_H));
                bl[nt2 * 2][0] = t0; bl[nt2 * 2][1] = t2;
                bl[nt2 * 2 + 1][0] = t1; bl[nt2 * 2 + 1][1] = t3;
            }
            // product 1: Ah*Bh
#pragma unroll
            for (int mt = 0; mt < 4; ++mt)
#pragma unroll
                for (int nt = 0; nt < 4; ++nt)
                    mma16816(acc[mt][nt], ah[mt], bh[nt]);
            // product 2: Ah*Bl
#pragma unroll
            for (int mt = 0; mt < 4; ++mt)
#pragma unroll
                for (int nt = 0; nt < 4; ++nt)
                    mma16816(acc[mt][nt], ah[mt], bl[nt]);
            // product 3: Al*Bh
#pragma unroll
            for (int mt = 0; mt < 4; ++mt)
#pragma unroll
                for (int nt = 0; nt < 4; ++nt)
                    mma16816(acc[mt][nt], al[mt], bh[nt]);
        }
    };

    const int nch = K >> 5;   // K-chunk = 32 (all K here are multiples of 32, nch >= 4)
    load_stage(0, 0); cp_commit();
    load_stage(1, 1); cp_commit();
    load_stage(2, 2); cp_commit();

    for (int it = 0; it < nch; ++it) {
        const int buf = it % 3;
        cp_wait2();
        __syncthreads();
        comp_chunk(buf);
        __syncthreads();
        if (it + 3 < nch) load_stage(buf, it + 3);
        cp_commit();
    }

    // ---------------- epilogue ----------------
#pragma unroll
    for (int mt = 0; mt < 4; ++mt) {
        const int mr = m0 + wm * 64 + mt * 16 + (lane >> 2);
#pragma unroll
        for (int hh = 0; hh < 2; ++hh) {
            const int m = mr + hh * 8;
            float fi = 0.0f, inv_rs = 0.0f;
            if (EPI == 2) {
                const long long ir = (long long)m;
                const long long s1 = ir * (ir + 1) / 2;
                const long long s2 = (long long)(NR - 1 - ir) * (NR - ir) / 2;
                inv_rs = 1.0f / (float)((long long)NR * NR - s1 - s2);
                fi = (float)ir;
            }
#pragma unroll
            for (int nt = 0; nt < 4; ++nt) {
                const int n = n0 + wn * 32 + nt * 8 + (lane & 3) * 2;
                const float v0 = acc[mt][nt][hh * 2 + 0];
                const float v1 = acc[mt][nt][hh * 2 + 1];
                if (EPI == 0) {
                    Cf[(size_t)m * ldc + n]     = v0;
                    Cf[(size_t)m * ldc + n + 1] = v1;
                } else if (EPI == 1) {
                    h16 a, b;
                    split2h(v0, a, b);
                    Ch[(size_t)m * ldc + n] = a; Cl[(size_t)m * ldc + n] = b;
                    split2h(v1, a, b);
                    Ch[(size_t)m * ldc + n + 1] = a; Cl[(size_t)m * ldc + n + 1] = b;
                } else {
#pragma unroll
                    for (int e = 0; e < 2; ++e) {
                        const int c = n + e;
                        const float Pt = Pp[(size_t)c * NR + (NR - 1)];
                        const float Qt = Qp[(size_t)c * NR + (NR - 1)];
                        const float Pi = Pp[(size_t)c * NR + m];
                        const float Qi = Qp[(size_t)c * NR + m];
                        const float numer =
                            ((float)NR + fi) * Pt - Qt - 2.0f * fi * Pi + 2.0f * Qi;
                        Cf[(size_t)m * ldc + c] =
                            0.5f * (e ? v1 : v0) + 0.5f * numer * inv_rs;
                    }
                }
            }
        }
    }
}

// ---------------------------------------------------------------------------
// fp16 split of a float array
// ---------------------------------------------------------------------------
__global__ void __launch_bounds__(256)
split_kernel(const float* __restrict__ src, h16* __restrict__ h,
             h16* __restrict__ l, int n)
{
    for (int i = blockIdx.x * 256 + threadIdx.x; i < n; i += gridDim.x * 256) {
        h16 hh, ll;
        split2h(src[i], hh, ll);
        h[i] = hh; l[i] = ll;
    }
}

// transpose + split: w[INSZ, NOUT] -> wT hi/lo [NOUT, INSZ]
__global__ void __launch_bounds__(256)
tsplit_kernel(const float* __restrict__ w, h16* __restrict__ h, h16* __restrict__ l)
{
    int idx = blockIdx.x * 256 + threadIdx.x;
    if (idx < INSZ * NOUT) {
        int o = idx / INSZ, in = idx % INSZ;
        h16 hh, ll;
        split2h(w[(size_t)in * NOUT + o], hh, ll);
        h[idx] = hh; l[idx] = ll;
    }
}

// ---------------------------------------------------------------------------
// Row softmax: read fp32 logits row, write h16 hi|lo P in place.
// Row i of g_S (32KB) becomes [8192 h16 hi][8192 h16 lo].
// ---------------------------------------------------------------------------
__global__ void __launch_bounds__(256)
softmax_split_kernel(float* __restrict__ S)
{
    __shared__ float row[NR];
    __shared__ float red[256];
    const int tid = threadIdx.x;
    float* Sr = S + (size_t)blockIdx.x * NR;

    float m = -1e30f;
    for (int t = tid; t < NR; t += 256) {
        float v = Sr[t];
        row[t] = v;
        m = fmaxf(m, v);
    }
    red[tid] = m;
    __syncthreads();
    for (int off = 128; off > 0; off >>= 1) {
        if (tid < off) red[tid] = fmaxf(red[tid], red[tid + off]);
        __syncthreads();
    }
    m = red[0];
    __syncthreads();

    float s = 0.0f;
    for (int t = tid; t < NR; t += 256) {
        float e = __expf(row[t] - m);
        row[t] = e;
        s += e;
    }
    red[tid] = s;
    __syncthreads();
    for (int off = 128; off > 0; off >>= 1) {
        if (tid < off) red[tid] += red[tid + off];
        __syncthreads();
    }
    const float inv = 1.0f / red[0];
    __syncthreads();

    h16* outh = (h16*)Sr;
    h16* outl = outh + NR;
    for (int t = tid; t < NR; t += 256) {
        h16 h, l;
        split2h(row[t] * inv, h, l);
        outh[t] = h; outl[t] = l;
    }
}

// ---------------------------------------------------------------------------
// Time-path column scan on v2T [NOUT, NR]: prefix sums of v and j*v (fp64).
// ---------------------------------------------------------------------------
__global__ void __launch_bounds__(256)
time_scan_kernel(const float* __restrict__ v2T,
                 float* __restrict__ Pp, float* __restrict__ Qp)
{
    __shared__ double sp[256];
    __shared__ double sq[256];
    __shared__ double carry[2];
    const int c   = blockIdx.x;
    const int tid = threadIdx.x;
    const float* v = v2T + (size_t)c * NR;

    if (tid == 0) { carry[0] = 0.0; carry[1] = 0.0; }
    __syncthreads();

    for (int chunk = 0; chunk < NR / 256; ++chunk) {
        const int row = chunk * 256 + tid;
        const double vv = (double)v[row];
        sp[tid] = vv;
        sq[tid] = (double)row * vv;
        __syncthreads();
        for (int off = 1; off < 256; off <<= 1) {
            double ap = 0.0, aq = 0.0;
            if (tid >= off) { ap = sp[tid - off]; aq = sq[tid - off]; }
            __syncthreads();
            if (tid >= off) { sp[tid] += ap; sq[tid] += aq; }
            __syncthreads();
        }
        const double p = sp[tid] + carry[0];
        const double q = sq[tid] + carry[1];
        Pp[(size_t)c * NR + row] = (float)p;
        Qp[(size_t)c * NR + row] = (float)q;
        __syncthreads();
        if (tid == 255) { carry[0] = p; carry[1] = q; }
        __syncthreads();
    }
}

// ---------------------------------------------------------------------------
extern "C" void kernel_launch(void* const* d_in, const int* in_sizes, int n_in,
                              void* d_out, int out_size)
{
    const float* x  = (const float*)d_in[0];   // [8192, 512]
    const float* W0 = (const float*)d_in[1];   // [128, 512]
    const float* W1 = (const float*)d_in[2];   // [128, 512]
    const float* w  = (const float*)d_in[3];   // [512, 512]
    const float* wt = (const float*)d_in[4];   // [512, 512]
    float* out = (float*)d_out;                // [8192, 512]

    cudaFuncSetAttribute(gemmH<0>, cudaFuncAttributeMaxDynamicSharedMemorySize, SMEM_DYN);
    cudaFuncSetAttribute(gemmH<1>, cudaFuncAttributeMaxDynamicSharedMemorySize, SMEM_DYN);
    cudaFuncSetAttribute(gemmH<2>, cudaFuncAttributeMaxDynamicSharedMemorySize, SMEM_DYN);

    h16 *xh, *xl, *W0h, *W0l, *W1h, *W1l, *wTh, *wTl, *wtTh, *wtTl;
    h16 *qh, *ql, *kh, *kl, *v1Th, *v1Tl;
    float *v2T, *S, *Pp, *Qp;
    cudaGetSymbolAddress((void**)&xh, g_xh);   cudaGetSymbolAddress((void**)&xl, g_xl);
    cudaGetSymbolAddress((void**)&W0h, g_W0h); cudaGetSymbolAddress((void**)&W0l, g_W0l);
    cudaGetSymbolAddress((void**)&W1h, g_W1h); cudaGetSymbolAddress((void**)&W1l, g_W1l);
    cudaGetSymbolAddress((void**)&wTh, g_wTh); cudaGetSymbolAddress((void**)&wTl, g_wTl);
    cudaGetSymbolAddress((void**)&wtTh, g_wtTh); cudaGetSymbolAddress((void**)&wtTl, g_wtTl);
    cudaGetSymbolAddress((void**)&qh, g_qh);   cudaGetSymbolAddress((void**)&ql, g_ql);
    cudaGetSymbolAddress((void**)&kh, g_kh);   cudaGetSymbolAddress((void**)&kl, g_kl);
    cudaGetSymbolAddress((void**)&v1Th, g_v1Th); cudaGetSymbolAddress((void**)&v1Tl, g_v1Tl);
    cudaGetSymbolAddress((void**)&v2T, g_v2T);
    cudaGetSymbolAddress((void**)&S, g_S);
    cudaGetSymbolAddress((void**)&Pp, g_Pp);   cudaGetSymbolAddress((void**)&Qp, g_Qp);

    // input splits
    split_kernel<<<2048, 256>>>(x, xh, xl, NR * INSZ);
    split_kernel<<<256, 256>>>(W0, W0h, W0l, FEAT * INSZ);
    split_kernel<<<256, 256>>>(W1, W1h, W1l, FEAT * INSZ);
    tsplit_kernel<<<(INSZ * NOUT + 255) / 256, 256>>>(w, wTh, wTl);
    tsplit_kernel<<<(INSZ * NOUT + 255) / 256, 256>>>(wt, wtTh, wtTl);

    // q = x @ W0^T, k = x @ W1^T  -> h16 pairs [8192,128]
    gemmH<1><<<dim3(1, NR / 128), 256, SMEM_DYN>>>(
        xh, xl, INSZ, W0h, W0l, INSZ, nullptr, qh, ql, FEAT, INSZ, nullptr, nullptr);
    gemmH<1><<<dim3(1, NR / 128), 256, SMEM_DYN>>>(
        xh, xl, INSZ, W1h, W1l, INSZ, nullptr, kh, kl, FEAT, INSZ, nullptr, nullptr);

    // v1T = w^T @ x^T -> h16 pairs [512, 8192] (B-operand form for final GEMM)
    gemmH<1><<<dim3(NR / 128, NOUT / 128), 256, SMEM_DYN>>>(
        wTh, wTl, INSZ, xh, xl, INSZ, nullptr, v1Th, v1Tl, NR, INSZ, nullptr, nullptr);

    // v2T = wt^T @ x^T -> fp32 [512, 8192]
    gemmH<0><<<dim3(NR / 128, NOUT / 128), 256, SMEM_DYN>>>(
        wtTh, wtTl, INSZ, xh, xl, INSZ, v2T, nullptr, nullptr, NR, INSZ, nullptr, nullptr);

    // time-path prefix sums
    time_scan_kernel<<<NOUT, 256>>>(v2T, Pp, Qp);

    // S = q @ k^T  fp32 [8192, 8192]
    gemmH<0><<<dim3(NR / 128, NR / 128), 256, SMEM_DYN>>>(
        qh, ql, FEAT, kh, kl, FEAT, S, nullptr, nullptr, NR, FEAT, nullptr, nullptr);

    // P = softmax(S) -> h16 hi|lo in place
    softmax_split_kernel<<<NR, 256>>>(S);

    // out = 0.5 * (P @ v1) + 0.5 * time-term  (fused epilogue)
    gemmH<2><<<dim3(NOUT / 128, NR / 128), 256, SMEM_DYN>>>(
        (const h16*)S, (const h16*)S + NR, 2 * NR,
        v1Th, v1Tl, NR, out, nullptr, nullptr, NOUT, NR, Pp, Qp);
}

// round 5
// speedup vs baseline: 2.8646x; 1.5686x over previous
#include <cuda_runtime.h>
#include <cuda_fp16.h>
#include <cstdint>

#define NR 8192
#define INSZ 512
#define FEAT 128
#define NOUT 512
#define CAP 2048
#define THRESH 20.0f

typedef __half h16;

// ---------------------------------------------------------------------------
// Scratch (static device globals — allocation-free per harness rules)
// ---------------------------------------------------------------------------
__device__ __align__(16) h16 g_xh[NR * INSZ], g_xl[NR * INSZ];
__device__ __align__(16) h16 g_W0h[FEAT * INSZ], g_W0l[FEAT * INSZ];
__device__ __align__(16) h16 g_W1h[FEAT * INSZ], g_W1l[FEAT * INSZ];
__device__ __align__(16) h16 g_wTh[NOUT * INSZ], g_wTl[NOUT * INSZ];
__device__ __align__(16) h16 g_wtTh[NOUT * INSZ], g_wtTl[NOUT * INSZ];
__device__ __align__(16) h16 g_qh[NR * FEAT], g_ql[NR * FEAT];
__device__ __align__(16) h16 g_kh[NR * FEAT], g_kl[NR * FEAT];
__device__ __align__(16) float g_v1[(size_t)NR * NOUT];     // fp32 x@w
__device__ __align__(16) float g_v2T[(size_t)NOUT * NR];
__device__ __align__(16) float g_S[(size_t)NR * NR];        // fp32 logits
__device__ __align__(16) float g_Pp[(size_t)NOUT * NR];
__device__ __align__(16) float g_Qp[(size_t)NOUT * NR];
__device__ __align__(16) float g_Ptot[NOUT], g_Qtot[NOUT];
__device__ __align__(16) uint16_t g_idx[(size_t)NR * CAP];
__device__ __align__(16) float    g_pv [(size_t)NR * CAP];
__device__ int g_cnt[NR];

// ---------------------------------------------------------------------------
// PTX helpers (base sm_103 target: cp.async / ldmatrix / mma.sync only)
// ---------------------------------------------------------------------------
__device__ __forceinline__ uint32_t smem_to_u32(const void* p) {
    uint32_t a;
    asm("{ .reg .u64 t; cvta.to.shared.u64 t, %1; cvt.u32.u64 %0, t; }" : "=r"(a) : "l"(p));
    return a;
}
__device__ __forceinline__ void cp16(uint32_t s, const void* g) {
    asm volatile("cp.async.cg.shared.global [%0], [%1], 16;" :: "r"(s), "l"(g));
}
__device__ __forceinline__ void cp_commit() { asm volatile("cp.async.commit_group;"); }
__device__ __forceinline__ void cp_wait2()  { asm volatile("cp.async.wait_group 2;"); }

__device__ __forceinline__ void ldm_x4(uint32_t& r0, uint32_t& r1, uint32_t& r2, uint32_t& r3,
                                       uint32_t addr) {
    asm volatile("ldmatrix.sync.aligned.m8n8.x4.shared.b16 {%0,%1,%2,%3}, [%4];"
                 : "=r"(r0), "=r"(r1), "=r"(r2), "=r"(r3) : "r"(addr));
}
__device__ __forceinline__ void mma16816(float* c, const uint32_t* a, const uint32_t* b) {
    asm volatile(
        "mma.sync.aligned.m16n8k16.row.col.f32.f16.f16.f32 "
        "{%0,%1,%2,%3}, {%4,%5,%6,%7}, {%8,%9}, {%0,%1,%2,%3};"
        : "+f"(c[0]), "+f"(c[1]), "+f"(c[2]), "+f"(c[3])
        : "r"(a[0]), "r"(a[1]), "r"(a[2]), "r"(a[3]), "r"(b[0]), "r"(b[1]));
}

__device__ __forceinline__ void split2h(float v, h16& h, h16& l) {
    h = __float2half_rn(v);
    l = __float2half_rn(v - __half2float(h));
}

// ---------------------------------------------------------------------------
// HMMA GEMM: C[M,N] = A[M,K] @ B[N,K]^T, A/B as fp16 (hi,lo), 3-product emu.
// CTA tile 128x128x32; 8 warps (2M x 4N); 3-stage cp.async.
// EPI: 0 fp32 store; 1 h16 hi/lo pair store.
// ---------------------------------------------------------------------------
#define STG   40960
#define OPA_H 0
#define OPA_L 10240
#define OPB_H 20480
#define OPB_L 30720
#define SMEM_DYN (3 * STG)

template <int EPI>
__global__ void __launch_bounds__(256, 1)
gemmH(const h16* __restrict__ Ah, const h16* __restrict__ Al, size_t lda,
      const h16* __restrict__ Bh, const h16* __restrict__ Bl, size_t ldb,
      float* __restrict__ Cf, h16* __restrict__ Ch, h16* __restrict__ Cl,
      size_t ldc, int K)
{
    extern __shared__ char smem[];
    const uint32_t sb = smem_to_u32(smem);
    const int tid  = threadIdx.x;
    const int lane = tid & 31, wid = tid >> 5;
    const int wm   = wid >> 2, wn = wid & 3;
    const int m0   = blockIdx.y * 128;
    const int n0   = blockIdx.x * 128;

    const int lrow = tid >> 1;
    const int lc0  = (tid & 1) * 2;

    float acc[4][4][4];
#pragma unroll
    for (int i = 0; i < 4; ++i)
#pragma unroll
        for (int j = 0; j < 4; ++j)
#pragma unroll
            for (int e = 0; e < 4; ++e) acc[i][j][e] = 0.0f;

    auto load_stage = [&](int buf, int chunk) {
        const size_t k0 = (size_t)chunk * 32;
        const uint32_t s0 = sb + buf * STG;
        const uint32_t so = (uint32_t)lrow * 80 + lc0 * 16;
        const h16* pAh = Ah + (size_t)(m0 + lrow) * lda + k0 + lc0 * 8;
        const h16* pAl = Al + (size_t)(m0 + lrow) * lda + k0 + lc0 * 8;
        const h16* pBh = Bh + (size_t)(n0 + lrow) * ldb + k0 + lc0 * 8;
        const h16* pBl = Bl + (size_t)(n0 + lrow) * ldb + k0 + lc0 * 8;
        cp16(s0 + OPA_H + so, pAh);      cp16(s0 + OPA_H + so + 16, pAh + 8);
        cp16(s0 + OPA_L + so, pAl);      cp16(s0 + OPA_L + so + 16, pAl + 8);
        cp16(s0 + OPB_H + so, pBh);      cp16(s0 + OPB_H + so + 16, pBh + 8);
        cp16(s0 + OPB_L + so, pBl);      cp16(s0 + OPB_L + so + 16, pBl + 8);
    };

    const int rsel = (lane & 7) + ((lane >> 3) & 1) * 8;
    const uint32_t koff_lane = ((lane >> 4) & 1) * 16;

    auto comp_chunk = [&](int buf) {
        const uint32_t base = sb + buf * STG;
#pragma unroll
        for (int sk = 0; sk < 2; ++sk) {
            uint32_t ah[4][4], al[4][4], bh[4][2], bl[4][2];
            const uint32_t koff = sk * 32 + koff_lane;
#pragma unroll
            for (int mt = 0; mt < 4; ++mt) {
                const uint32_t ra =
                    base + OPA_H + (uint32_t)(wm * 64 + mt * 16 + rsel) * 80 + koff;
                ldm_x4(ah[mt][0], ah[mt][1], ah[mt][2], ah[mt][3], ra);
                ldm_x4(al[mt][0], al[mt][1], al[mt][2], al[mt][3], ra + (OPA_L - OPA_H));
            }
#pragma unroll
            for (int nt2 = 0; nt2 < 2; ++nt2) {
                const uint32_t rb =
                    base + OPB_H + (uint32_t)(wn * 32 + nt2 * 16 + rsel) * 80 + koff;
                uint32_t t0, t1, t2, t3;
                ldm_x4(t0, t1, t2, t3, rb);
                bh[nt2 * 2][0] = t0; bh[nt2 * 2][1] = t2;
                bh[nt2 * 2 + 1][0] = t1; bh[nt2 * 2 + 1][1] = t3;
                ldm_x4(t0, t1, t2, t3, rb + (OPB_L - OPB_H));
                bl[nt2 * 2][0] = t0; bl[nt2 * 2][1] = t2;
                bl[nt2 * 2 + 1][0] = t1; bl[nt2 * 2 + 1][1] = t3;
            }
#pragma unroll
            for (int mt = 0; mt < 4; ++mt)
#pragma unroll
                for (int nt = 0; nt < 4; ++nt)
                    mma16816(acc[mt][nt], ah[mt], bh[nt]);
#pragma unroll
            for (int mt = 0; mt < 4; ++mt)
#pragma unroll
                for (int nt = 0; nt < 4; ++nt)
                    mma16816(acc[mt][nt], ah[mt], bl[nt]);
#pragma unroll
            for (int mt = 0; mt < 4; ++mt)
#pragma unroll
                for (int nt = 0; nt < 4; ++nt)
                    mma16816(acc[mt][nt], al[mt], bh[nt]);
        }
    };

    const int nch = K >> 5;
    load_stage(0, 0); cp_commit();
    load_stage(1, 1); cp_commit();
    load_stage(2, 2); cp_commit();

    for (int it = 0; it < nch; ++it) {
        const int buf = it % 3;
        cp_wait2();
        __syncthreads();
        comp_chunk(buf);
        __syncthreads();
        if (it + 3 < nch) load_stage(buf, it + 3);
        cp_commit();
    }

#pragma unroll
    for (int mt = 0; mt < 4; ++mt) {
        const int mr = m0 + wm * 64 + mt * 16 + (lane >> 2);
#pragma unroll
        for (int hh = 0; hh < 2; ++hh) {
            const int m = mr + hh * 8;
#pragma unroll
            for (int nt = 0; nt < 4; ++nt) {
                const int n = n0 + wn * 32 + nt * 8 + (lane & 3) * 2;
                const float v0 = acc[mt][nt][hh * 2 + 0];
                const float v1 = acc[mt][nt][hh * 2 + 1];
                if (EPI == 0) {
                    Cf[(size_t)m * ldc + n]     = v0;
                    Cf[(size_t)m * ldc + n + 1] = v1;
                } else {
                    h16 a, b;
                    split2h(v0, a, b);
                    Ch[(size_t)m * ldc + n] = a; Cl[(size_t)m * ldc + n] = b;
                    split2h(v1, a, b);
                    Ch[(size_t)m * ldc + n + 1] = a; Cl[(size_t)m * ldc + n + 1] = b;
                }
            }
        }
    }
}

// ---------------------------------------------------------------------------
__global__ void __launch_bounds__(256)
split_kernel(const float* __restrict__ src, h16* __restrict__ h,
             h16* __restrict__ l, int n)
{
    for (int i = blockIdx.x * 256 + threadIdx.x; i < n; i += gridDim.x * 256) {
        h16 hh, ll;
        split2h(src[i], hh, ll);
        h[i] = hh; l[i] = ll;
    }
}

__global__ void __launch_bounds__(256)
tsplit_kernel(const float* __restrict__ w, h16* __restrict__ h, h16* __restrict__ l)
{
    int idx = blockIdx.x * 256 + threadIdx.x;
    if (idx < INSZ * NOUT) {
        int o = idx / INSZ, in = idx % INSZ;
        h16 hh, ll;
        split2h(w[(size_t)in * NOUT + o], hh, ll);
        h[idx] = hh; l[idx] = ll;
    }
}

// ---------------------------------------------------------------------------
// Softmax + deterministic compaction: per row, keep entries with s > max-THRESH,
// normalized by the FULL row sum. Emits (uint16 idx, fp32 p) compact lists.
// ---------------------------------------------------------------------------
__global__ void __launch_bounds__(256)
softmax_compact_kernel(const float* __restrict__ S,
                       uint16_t* __restrict__ gidx, float* __restrict__ gpv,
                       int* __restrict__ gcnt)
{
    __shared__ float row[NR];       // 32KB
    __shared__ float red[256];
    __shared__ int   scn[256];
    const int tid = threadIdx.x;
    const int r   = blockIdx.x;
    const float* Sr = S + (size_t)r * NR;

    float m = -1e30f;
    for (int t = tid; t < NR; t += 256) {
        float v = Sr[t];
        row[t] = v;
        m = fmaxf(m, v);
    }
    red[tid] = m;
    __syncthreads();
    for (int off = 128; off > 0; off >>= 1) {
        if (tid < off) red[tid] = fmaxf(red[tid], red[tid + off]);
        __syncthreads();
    }
    m = red[0];
    __syncthreads();

    float s = 0.0f;
    for (int t = tid; t < NR; t += 256)
        s += __expf(row[t] - m);
    red[tid] = s;
    __syncthreads();
    for (int off = 128; off > 0; off >>= 1) {
        if (tid < off) red[tid] += red[tid + off];
        __syncthreads();
    }
    const float inv = 1.0f / red[0];
    const float thresh = m - THRESH;
    __syncthreads();

    // deterministic compaction: per-thread count -> smem scan -> ordered write
    int local = 0;
    for (int t = tid; t < NR; t += 256)
        if (row[t] > thresh) ++local;
    scn[tid] = local;
    __syncthreads();
    for (int off = 1; off < 256; off <<= 1) {
        int v = (tid >= off) ? scn[tid - off] : 0;
        __syncthreads();
        scn[tid] += v;
        __syncthreads();
    }
    int pos = scn[tid] - local;      // exclusive prefix
    const int total = scn[255];

    uint16_t* ri = gidx + (size_t)r * CAP;
    float*    rp = gpv  + (size_t)r * CAP;
    for (int t = tid; t < NR; t += 256) {
        const float v = row[t];
        if (v > thresh) {
            if (pos < CAP) {
                ri[pos] = (uint16_t)t;
                rp[pos] = __expf(v - m) * inv;
            }
            ++pos;
        }
    }
    if (tid == 0) gcnt[r] = total < CAP ? total : CAP;
}

// ---------------------------------------------------------------------------
// Sparse attn apply: out[m,:] = 0.5 * sum_e p_e * v1[idx_e, :]
// one block (128 thr) per row, each thread owns a float4 of output cols.
// ---------------------------------------------------------------------------
__global__ void __launch_bounds__(128)
spmm_kernel(const uint16_t* __restrict__ gidx, const float* __restrict__ gpv,
            const int* __restrict__ gcnt, const float* __restrict__ v1,
            float* __restrict__ out)
{
    __shared__ uint16_t sidx[512];
    __shared__ float    sp[512];
    const int m   = blockIdx.x;
    const int tid = threadIdx.x;
    const uint16_t* ri = gidx + (size_t)m * CAP;
    const float*    rp = gpv  + (size_t)m * CAP;
    const int n = gcnt[m];

    float4 acc = make_float4(0.f, 0.f, 0.f, 0.f);
    for (int base = 0; base < n; base += 512) {
        const int c = min(512, n - base);
        __syncthreads();
        for (int t = tid; t < c; t += 128) {
            sidx[t] = ri[base + t];
            sp[t]   = rp[base + t];
        }
        __syncthreads();
        int e = 0;
        for (; e + 4 <= c; e += 4) {
            const float p0 = sp[e], p1 = sp[e + 1], p2 = sp[e + 2], p3 = sp[e + 3];
            const float4 a0 = *(const float4*)(v1 + (size_t)sidx[e]     * NOUT + tid * 4);
            const float4 a1 = *(const float4*)(v1 + (size_t)sidx[e + 1] * NOUT + tid * 4);
            const float4 a2 = *(const float4*)(v1 + (size_t)sidx[e + 2] * NOUT + tid * 4);
            const float4 a3 = *(const float4*)(v1 + (size_t)sidx[e + 3] * NOUT + tid * 4);
            acc.x += p0 * a0.x + p1 * a1.x + p2 * a2.x + p3 * a3.x;
            acc.y += p0 * a0.y + p1 * a1.y + p2 * a2.y + p3 * a3.y;
            acc.z += p0 * a0.z + p1 * a1.z + p2 * a2.z + p3 * a3.z;
            acc.w += p0 * a0.w + p1 * a1.w + p2 * a2.w + p3 * a3.w;
        }
        for (; e < c; ++e) {
            const float p = sp[e];
            const float4 a = *(const float4*)(v1 + (size_t)sidx[e] * NOUT + tid * 4);
            acc.x += p * a.x; acc.y += p * a.y; acc.z += p * a.z; acc.w += p * a.w;
        }
    }
    *(float4*)(out + (size_t)m * NOUT + tid * 4) =
        make_float4(0.5f * acc.x, 0.5f * acc.y, 0.5f * acc.z, 0.5f * acc.w);
}

// ---------------------------------------------------------------------------
// Time-path column scan on v2T [NOUT, NR]: prefix sums of v and j*v (fp64).
// Also records per-column totals.
// ---------------------------------------------------------------------------
__global__ void __launch_bounds__(256)
time_scan_kernel(const float* __restrict__ v2T,
                 float* __restrict__ Pp, float* __restrict__ Qp,
                 float* __restrict__ Ptot, float* __restrict__ Qtot)
{
    __shared__ double sp[256];
    __shared__ double sq[256];
    __shared__ double carry[2];
    const int c   = blockIdx.x;
    const int tid = threadIdx.x;
    const float* v = v2T + (size_t)c * NR;

    if (tid == 0) { carry[0] = 0.0; carry[1] = 0.0; }
    __syncthreads();

    for (int chunk = 0; chunk < NR / 256; ++chunk) {
        const int row = chunk * 256 + tid;
        const double vv = (double)v[row];
        sp[tid] = vv;
        sq[tid] = (double)row * vv;
        __syncthreads();
        for (int off = 1; off < 256; off <<= 1) {
            double ap = 0.0, aq = 0.0;
            if (tid >= off) { ap = sp[tid - off]; aq = sq[tid - off]; }
            __syncthreads();
            if (tid >= off) { sp[tid] += ap; sq[tid] += aq; }
            __syncthreads();
        }
        const double p = sp[tid] + carry[0];
        const double q = sq[tid] + carry[1];
        Pp[(size_t)c * NR + row] = (float)p;
        Qp[(size_t)c * NR + row] = (float)q;
        __syncthreads();
        if (tid == 255) {
            carry[0] = p; carry[1] = q;
            if (chunk == NR / 256 - 1) { Ptot[c] = (float)p; Qtot[c] = (float)q; }
        }
        __syncthreads();
    }
}

// ---------------------------------------------------------------------------
// Time-path add: out[m,c] += 0.5 * time(m,c); tiled transpose reads of Pp/Qp.
// Block (32,8); tile 32m x 32c. tp[i][tx] holds Pp[(c0+i)][m0+tx]; the value
// for (m=m0+i, c=c0+tx) is therefore tp[tx][i] (transposed access, 33-pad).
// ---------------------------------------------------------------------------
__global__ void __launch_bounds__(256)
time_add_kernel(float* __restrict__ out,
                const float* __restrict__ Pp, const float* __restrict__ Qp,
                const float* __restrict__ Ptot, const float* __restrict__ Qtot)
{
    __shared__ float tp[32][33], tq[32][33];
    const int tx = threadIdx.x;     // 0..31
    const int ty = threadIdx.y;     // 0..7
    const int c0 = blockIdx.x * 32;
    const int m0 = blockIdx.y * 32;

#pragma unroll
    for (int i = ty; i < 32; i += 8) {
        tp[i][tx] = Pp[(size_t)(c0 + i) * NR + m0 + tx];
        tq[i][tx] = Qp[(size_t)(c0 + i) * NR + m0 + tx];
    }
    __syncthreads();

#pragma unroll
    for (int i = ty; i < 32; i += 8) {
        const int m = m0 + i;
        const int c = c0 + tx;
        const long long ir = (long long)m;
        const long long s1 = ir * (ir + 1) / 2;
        const long long s2 = (long long)(NR - 1 - ir) * (NR - ir) / 2;
        const float inv_rs = 1.0f / (float)((long long)NR * NR - s1 - s2);
        const float fi = (float)m;
        const float numer = ((float)NR + fi) * Ptot[c] - Qtot[c]
                          - 2.0f * fi * tp[tx][i] + 2.0f * tq[tx][i];
        out[(size_t)m * NOUT + c] += 0.5f * numer * inv_rs;
    }
}

// ---------------------------------------------------------------------------
extern "C" void kernel_launch(void* const* d_in, const int* in_sizes, int n_in,
                              void* d_out, int out_size)
{
    const float* x  = (const float*)d_in[0];
    const float* W0 = (const float*)d_in[1];
    const float* W1 = (const float*)d_in[2];
    const float* w  = (const float*)d_in[3];
    const float* wt = (const float*)d_in[4];
    float* out = (float*)d_out;

    cudaFuncSetAttribute(gemmH<0>, cudaFuncAttributeMaxDynamicSharedMemorySize, SMEM_DYN);
    cudaFuncSetAttribute(gemmH<1>, cudaFuncAttributeMaxDynamicSharedMemorySize, SMEM_DYN);

    h16 *xh, *xl, *W0h, *W0l, *W1h, *W1l, *wTh, *wTl, *wtTh, *wtTl;
    h16 *qh, *ql, *kh, *kl;
    float *v1, *v2T, *S, *Pp, *Qp, *Ptot, *Qtot, *pv;
    uint16_t* idx;
    int* cnt;
    cudaGetSymbolAddress((void**)&xh, g_xh);   cudaGetSymbolAddress((void**)&xl, g_xl);
    cudaGetSymbolAddress((void**)&W0h, g_W0h); cudaGetSymbolAddress((void**)&W0l, g_W0l);
    cudaGetSymbolAddress((void**)&W1h, g_W1h); cudaGetSymbolAddress((void**)&W1l, g_W1l);
    cudaGetSymbolAddress((void**)&wTh, g_wTh); cudaGetSymbolAddress((void**)&wTl, g_wTl);
    cudaGetSymbolAddress((void**)&wtTh, g_wtTh); cudaGetSymbolAddress((void**)&wtTl, g_wtTl);
    cudaGetSymbolAddress((void**)&qh, g_qh);   cudaGetSymbolAddress((void**)&ql, g_ql);
    cudaGetSymbolAddress((void**)&kh, g_kh);   cudaGetSymbolAddress((void**)&kl, g_kl);
    cudaGetSymbolAddress((void**)&v1, g_v1);
    cudaGetSymbolAddress((void**)&v2T, g_v2T);
    cudaGetSymbolAddress((void**)&S, g_S);
    cudaGetSymbolAddress((void**)&Pp, g_Pp);   cudaGetSymbolAddress((void**)&Qp, g_Qp);
    cudaGetSymbolAddress((void**)&Ptot, g_Ptot); cudaGetSymbolAddress((void**)&Qtot, g_Qtot);
    cudaGetSymbolAddress((void**)&idx, g_idx);
    cudaGetSymbolAddress((void**)&pv, g_pv);
    cudaGetSymbolAddress((void**)&cnt, g_cnt);

    // input splits
    split_kernel<<<2048, 256>>>(x, xh, xl, NR * INSZ);
    split_kernel<<<256, 256>>>(W0, W0h, W0l, FEAT * INSZ);
    split_kernel<<<256, 256>>>(W1, W1h, W1l, FEAT * INSZ);
    tsplit_kernel<<<(INSZ * NOUT + 255) / 256, 256>>>(w, wTh, wTl);
    tsplit_kernel<<<(INSZ * NOUT + 255) / 256, 256>>>(wt, wtTh, wtTl);

    // q = x @ W0^T, k = x @ W1^T  -> h16 pairs [8192,128]
    gemmH<1><<<dim3(1, NR / 128), 256, SMEM_DYN>>>(
        xh, xl, INSZ, W0h, W0l, INSZ, nullptr, qh, ql, FEAT, INSZ);
    gemmH<1><<<dim3(1, NR / 128), 256, SMEM_DYN>>>(
        xh, xl, INSZ, W1h, W1l, INSZ, nullptr, kh, kl, FEAT, INSZ);

    // v1 = x @ w -> fp32 [8192, 512]  (row-gatherable by SpMM)
    gemmH<0><<<dim3(NOUT / 128, NR / 128), 256, SMEM_DYN>>>(
        xh, xl, INSZ, wTh, wTl, INSZ, v1, nullptr, nullptr, NOUT, INSZ);

    // v2T = wt^T @ x^T -> fp32 [512, 8192]
    gemmH<0><<<dim3(NR / 128, NOUT / 128), 256, SMEM_DYN>>>(
        wtTh, wtTl, INSZ, xh, xl, INSZ, v2T, nullptr, nullptr, NR, INSZ);

    // time-path prefix sums + totals
    time_scan_kernel<<<NOUT, 256>>>(v2T, Pp, Qp, Ptot, Qtot);

    // S = q @ k^T  fp32 [8192, 8192]
    gemmH<0><<<dim3(NR / 128, NR / 128), 256, SMEM_DYN>>>(
        qh, ql, FEAT, kh, kl, FEAT, S, nullptr, nullptr, NR, FEAT);

    // softmax + top-mass compaction
    softmax_compact_kernel<<<NR, 256>>>(S, idx, pv, cnt);

    // out = 0.5 * (P_sparse @ v1)
    spmm_kernel<<<NR, 128>>>(idx, pv, cnt, v1, out);

    // out += 0.5 * time-path
    time_add_kernel<<<dim3(NOUT / 32, NR / 32), dim3(32, 8)>>>(out, Pp, Qp, Ptot, Qtot);
}

// round 7
// speedup vs baseline: 4.3151x; 1.5064x over previous
#include <cuda_runtime.h>
#include <cuda_fp16.h>
#include <cstdint>

#define NR 8192
#define INSZ 512
#define FEAT 128
#define NOUT 512
#define CAP 2048
#define THRESH_S 18.1f

typedef __half h16;

// ---------------------------------------------------------------------------
// Scratch (static device globals — allocation-free per harness rules)
// ---------------------------------------------------------------------------
__device__ __align__(16) h16 g_xh[NR * INSZ], g_xl[NR * INSZ];
__device__ __align__(16) h16 g_Wqkh[2 * FEAT * INSZ], g_Wqkl[2 * FEAT * INSZ];
__device__ __align__(16) h16 g_wTh[NOUT * INSZ], g_wTl[NOUT * INSZ];
__device__ __align__(16) h16 g_wtTh[NOUT * INSZ], g_wtTl[NOUT * INSZ];
__device__ __align__(16) float g_qkf[(size_t)NR * 256];   // fp32 q|k  [8192, 256]
__device__ __align__(16) h16   g_qkh[(size_t)NR * 256];   // fp16 q|k
__device__ __align__(16) h16   g_v1h[(size_t)NR * NOUT];  // fp16 x@w
__device__ __align__(16) float g_v2T[(size_t)NOUT * NR];
__device__ __align__(16) h16   g_Sh[(size_t)NR * NR];     // fp16 screening logits
__device__ __align__(16) float g_Pp[(size_t)NOUT * NR];
__device__ __align__(16) float g_Qp[(size_t)NOUT * NR];
__device__ __align__(16) float g_Ptot[NOUT], g_Qtot[NOUT];
__device__ __align__(16) uint16_t g_idx[(size_t)NR * CAP];
__device__ __align__(16) float    g_pv [(size_t)NR * CAP];
__device__ int g_cnt[NR];

// ---------------------------------------------------------------------------
// PTX helpers (base sm_103 target: cp.async / ldmatrix / mma.sync only)
// ---------------------------------------------------------------------------
__device__ __forceinline__ uint32_t smem_to_u32(const void* p) {
    uint32_t a;
    asm("{ .reg .u64 t; cvta.to.shared.u64 t, %1; cvt.u32.u64 %0, t; }" : "=r"(a) : "l"(p));
    return a;
}
__device__ __forceinline__ void cp16(uint32_t s, const void* g) {
    asm volatile("cp.async.cg.shared.global [%0], [%1], 16;" :: "r"(s), "l"(g));
}
__device__ __forceinline__ void cp_commit() { asm volatile("cp.async.commit_group;"); }
__device__ __forceinline__ void cp_wait2()  { asm volatile("cp.async.wait_group 2;"); }

__device__ __forceinline__ void ldm_x4(uint32_t& r0, uint32_t& r1, uint32_t& r2, uint32_t& r3,
                                       uint32_t addr) {
    asm volatile("ldmatrix.sync.aligned.m8n8.x4.shared.b16 {%0,%1,%2,%3}, [%4];"
                 : "=r"(r0), "=r"(r1), "=r"(r2), "=r"(r3) : "r"(addr));
}
__device__ __forceinline__ void mma16816(float* c, const uint32_t* a, const uint32_t* b) {
    asm volatile(
        "mma.sync.aligned.m16n8k16.row.col.f32.f16.f16.f32 "
        "{%0,%1,%2,%3}, {%4,%5,%6,%7}, {%8,%9}, {%0,%1,%2,%3};"
        : "+f"(c[0]), "+f"(c[1]), "+f"(c[2]), "+f"(c[3])
        : "r"(a[0]), "r"(a[1]), "r"(a[2]), "r"(a[3]), "r"(b[0]), "r"(b[1]));
}

__device__ __forceinline__ void split2h(float v, h16& h, h16& l) {
    h = __float2half_rn(v);
    l = __float2half_rn(v - __half2float(h));
}

// ---------------------------------------------------------------------------
// HMMA GEMM: C[M,N] = A[M,K] @ B[N,K]^T.
// PROD=3: hi/lo 3-product emulation. PROD=1: single hi*hi product.
// EPI: 0 = fp32 store; 3 = fp16 store; 4 = fp32 + fp16 dual store.
// CTA tile 128x128x32; 8 warps (2M x 4N); 3-stage cp.async.
// ---------------------------------------------------------------------------
template <int EPI, int PROD>
__global__ void __launch_bounds__(256, 1)
gemmH(const h16* __restrict__ Ah, const h16* __restrict__ Al, size_t lda,
      const h16* __restrict__ Bh, const h16* __restrict__ Bl, size_t ldb,
      float* __restrict__ Cf, h16* __restrict__ Ch, size_t ldc, int K)
{
    constexpr uint32_t STG_ = (PROD == 3) ? 40960u : 20480u;
    constexpr uint32_t OA_H = 0;
    constexpr uint32_t OA_L = 10240;
    constexpr uint32_t OB_H = (PROD == 3) ? 20480u : 10240u;
    constexpr uint32_t OB_L = 30720;

    extern __shared__ char smem[];
    const uint32_t sb = smem_to_u32(smem);
    const int tid  = threadIdx.x;
    const int lane = tid & 31, wid = tid >> 5;
    const int wm   = wid >> 2, wn = wid & 3;
    const int m0   = blockIdx.y * 128;
    const int n0   = blockIdx.x * 128;

    const int lrow = tid >> 1;
    const int lc0  = (tid & 1) * 2;

    float acc[4][4][4];
#pragma unroll
    for (int i = 0; i < 4; ++i)
#pragma unroll
        for (int j = 0; j < 4; ++j)
#pragma unroll
            for (int e = 0; e < 4; ++e) acc[i][j][e] = 0.0f;

    auto load_stage = [&](int buf, int chunk) {
        const size_t k0 = (size_t)chunk * 32;
        const uint32_t s0 = sb + buf * STG_;
        const uint32_t so = (uint32_t)lrow * 80 + lc0 * 16;
        const h16* pAh = Ah + (size_t)(m0 + lrow) * lda + k0 + lc0 * 8;
        const h16* pBh = Bh + (size_t)(n0 + lrow) * ldb + k0 + lc0 * 8;
        cp16(s0 + OA_H + so, pAh);  cp16(s0 + OA_H + so + 16, pAh + 8);
        cp16(s0 + OB_H + so, pBh);  cp16(s0 + OB_H + so + 16, pBh + 8);
        if (PROD == 3) {
            const h16* pAl = Al + (size_t)(m0 + lrow) * lda + k0 + lc0 * 8;
            const h16* pBl = Bl + (size_t)(n0 + lrow) * ldb + k0 + lc0 * 8;
            cp16(s0 + OA_L + so, pAl);  cp16(s0 + OA_L + so + 16, pAl + 8);
            cp16(s0 + OB_L + so, pBl);  cp16(s0 + OB_L + so + 16, pBl + 8);
        }
    };

    const int rsel = (lane & 7) + ((lane >> 3) & 1) * 8;
    const uint32_t koff_lane = ((lane >> 4) & 1) * 16;

    auto comp_chunk = [&](int buf) {
        const uint32_t base = sb + buf * STG_;
#pragma unroll
        for (int sk = 0; sk < 2; ++sk) {
            uint32_t ah[4][4], al[4][4], bh[4][2], bl[4][2];
            const uint32_t koff = sk * 32 + koff_lane;
#pragma unroll
            for (int mt = 0; mt < 4; ++mt) {
                const uint32_t ra =
                    base + OA_H + (uint32_t)(wm * 64 + mt * 16 + rsel) * 80 + koff;
                ldm_x4(ah[mt][0], ah[mt][1], ah[mt][2], ah[mt][3], ra);
                if (PROD == 3)
                    ldm_x4(al[mt][0], al[mt][1], al[mt][2], al[mt][3], ra + (OA_L - OA_H));
            }
#pragma unroll
            for (int nt2 = 0; nt2 < 2; ++nt2) {
                const uint32_t rb =
                    base + OB_H + (uint32_t)(wn * 32 + nt2 * 16 + rsel) * 80 + koff;
                uint32_t t0, t1, t2, t3;
                ldm_x4(t0, t1, t2, t3, rb);
                bh[nt2 * 2][0] = t0; bh[nt2 * 2][1] = t2;
                bh[nt2 * 2 + 1][0] = t1; bh[nt2 * 2 + 1][1] = t3;
                if (PROD == 3) {
                    ldm_x4(t0, t1, t2, t3, rb + (OB_L - OB_H));
                    bl[nt2 * 2][0] = t0; bl[nt2 * 2][1] = t2;
                    bl[nt2 * 2 + 1][0] = t1; bl[nt2 * 2 + 1][1] = t3;
                }
            }
#pragma unroll
            for (int mt = 0; mt < 4; ++mt)
#pragma unroll
                for (int nt = 0; nt < 4; ++nt)
                    mma16816(acc[mt][nt], ah[mt], bh[nt]);
            if (PROD == 3) {
#pragma unroll
                for (int mt = 0; mt < 4; ++mt)
#pragma unroll
                    for (int nt = 0; nt < 4; ++nt)
                        mma16816(acc[mt][nt], ah[mt], bl[nt]);
#pragma unroll
                for (int mt = 0; mt < 4; ++mt)
#pragma unroll
                    for (int nt = 0; nt < 4; ++nt)
                        mma16816(acc[mt][nt], al[mt], bh[nt]);
            }
        }
    };

    const int nch = K >> 5;
    load_stage(0, 0); cp_commit();
    load_stage(1, 1); cp_commit();
    load_stage(2, 2); cp_commit();

    for (int it = 0; it < nch; ++it) {
        const int buf = it % 3;
        cp_wait2();
        __syncthreads();
        comp_chunk(buf);
        __syncthreads();
        if (it + 3 < nch) load_stage(buf, it + 3);
        cp_commit();
    }

#pragma unroll
    for (int mt = 0; mt < 4; ++mt) {
        const int mr = m0 + wm * 64 + mt * 16 + (lane >> 2);
#pragma unroll
        for (int hh = 0; hh < 2; ++hh) {
            const int m = mr + hh * 8;
#pragma unroll
            for (int nt = 0; nt < 4; ++nt) {
                const int n = n0 + wn * 32 + nt * 8 + (lane & 3) * 2;
                const float v0 = acc[mt][nt][hh * 2 + 0];
                const float v1 = acc[mt][nt][hh * 2 + 1];
                if (EPI == 0 || EPI == 4)
                    *(float2*)(Cf + (size_t)m * ldc + n) = make_float2(v0, v1);
                if (EPI == 3 || EPI == 4)
                    *(__half2*)(Ch + (size_t)m * ldc + n) = __floats2half2_rn(v0, v1);
            }
        }
    }
}

// ---------------------------------------------------------------------------
__global__ void __launch_bounds__(256)
split_kernel(const float* __restrict__ src, h16* __restrict__ h,
             h16* __restrict__ l, int n)
{
    for (int i = blockIdx.x * 256 + threadIdx.x; i < n; i += gridDim.x * 256) {
        h16 hh, ll;
        split2h(src[i], hh, ll);
        h[i] = hh; l[i] = ll;
    }
}

__global__ void __launch_bounds__(256)
tsplit_kernel(const float* __restrict__ w, h16* __restrict__ h, h16* __restrict__ l)
{
    int idx = blockIdx.x * 256 + threadIdx.x;
    if (idx < INSZ * NOUT) {
        int o = idx / INSZ, in = idx % INSZ;
        h16 hh, ll;
        split2h(w[(size_t)in * NOUT + o], hh, ll);
        h[idx] = hh; l[idx] = ll;
    }
}

// ---------------------------------------------------------------------------
// Screening softmax + exact recompute:
//  1. find row max of fp16 screening logits; keep t where s > max - 18.1
//  2. recompute exact fp32 logits q[r].k[t] for survivors
//  3. softmax over survivors (dropped tail mass ~1e-6 relative)
// CAP=2048: with THRESH 18.1, truncation requires row max < 25.7 (P ~ e^-95).
// ---------------------------------------------------------------------------
__global__ void __launch_bounds__(256)
softmax_compact2(const h16* __restrict__ S, const float* __restrict__ qkf,
                 uint16_t* __restrict__ gidx, float* __restrict__ gpv,
                 int* __restrict__ gcnt)
{
    __shared__ h16   row[NR];          // 16 KB
    __shared__ float red[256];
    __shared__ int   scn[256];
    __shared__ uint16_t kidx[CAP];     // 4 KB
    __shared__ float klog[CAP];        // 8 KB
    __shared__ float qrow[FEAT];
    const int tid = threadIdx.x;
    const int r   = blockIdx.x;
    const h16* Sr = S + (size_t)r * NR;

    float m = -1e30f;
    for (int b = tid * 4; b < NR; b += 1024) {
        uint2 wv = *(const uint2*)(Sr + b);
        *(uint2*)(row + b) = wv;
        float2 f0 = __half22float2(*(__half2*)&wv.x);
        float2 f1 = __half22float2(*(__half2*)&wv.y);
        m = fmaxf(m, fmaxf(fmaxf(f0.x, f0.y), fmaxf(f1.x, f1.y)));
    }
    red[tid] = m;
    __syncthreads();
    for (int off = 128; off > 0; off >>= 1) {
        if (tid < off) red[tid] = fmaxf(red[tid], red[tid + off]);
        __syncthreads();
    }
    m = red[0];
    const float thresh = m - THRESH_S;
    __syncthreads();

    // deterministic compaction of survivor indices
    int local = 0;
    for (int t = tid; t < NR; t += 256)
        if (__half2float(row[t]) > thresh) ++local;
    scn[tid] = local;
    __syncthreads();
    for (int off = 1; off < 256; off <<= 1) {
        int v = (tid >= off) ? scn[tid - off] : 0;
        __syncthreads();
        scn[tid] += v;
        __syncthreads();
    }
    int pos = scn[tid] - local;
    const int n = min(scn[255], CAP);
    for (int t = tid; t < NR; t += 256)
        if (__half2float(row[t]) > thresh) {
            if (pos < CAP) kidx[pos] = (uint16_t)t;
            ++pos;
        }
    if (tid < FEAT) qrow[tid] = qkf[(size_t)r * 256 + tid];
    __syncthreads();

    // exact fp32 logits, warp per survivor
    const int lane = tid & 31, wid = tid >> 5;
    for (int e = wid; e < n; e += 8) {
        const float* kr = qkf + (size_t)kidx[e] * 256 + 128;
        float s = 0.0f;
#pragma unroll
        for (int j = 0; j < 4; ++j)
            s += qrow[lane + j * 32] * kr[lane + j * 32];
#pragma unroll
        for (int off = 16; off > 0; off >>= 1)
            s += __shfl_xor_sync(0xFFFFFFFFu, s, off);
        if (lane == 0) klog[e] = s;
    }
    __syncthreads();

    float m2 = -1e30f;
    for (int e = tid; e < n; e += 256) m2 = fmaxf(m2, klog[e]);
    red[tid] = m2;
    __syncthreads();
    for (int off = 128; off > 0; off >>= 1) {
        if (tid < off) red[tid] = fmaxf(red[tid], red[tid + off]);
        __syncthreads();
    }
    m2 = red[0];
    __syncthreads();

    float s = 0.0f;
    for (int e = tid; e < n; e += 256) s += expf(klog[e] - m2);
    red[tid] = s;
    __syncthreads();
    for (int off = 128; off > 0; off >>= 1) {
        if (tid < off) red[tid] += red[tid + off];
        __syncthreads();
    }
    const float inv = 1.0f / red[0];

    for (int e = tid; e < n; e += 256) {
        gidx[(size_t)r * CAP + e] = kidx[e];
        gpv [(size_t)r * CAP + e] = expf(klog[e] - m2) * inv;
    }
    if (tid == 0) gcnt[r] = n;
}

// ---------------------------------------------------------------------------
// Sparse attn apply on fp16 v1: out[m,:] = 0.5 * sum_e p_e * v1[idx_e,:]
// ---------------------------------------------------------------------------
__global__ void __launch_bounds__(128)
spmm_h(const uint16_t* __restrict__ gidx, const float* __restrict__ gpv,
       const int* __restrict__ gcnt, const h16* __restrict__ v1h,
       float* __restrict__ out)
{
    __shared__ uint16_t sidx[256];
    __shared__ float    sp[256];
    const int m   = blockIdx.x;
    const int tid = threadIdx.x;
    const int n   = gcnt[m];
    const uint16_t* ri = gidx + (size_t)m * CAP;
    const float*    rp = gpv  + (size_t)m * CAP;

    float4 acc = make_float4(0.f, 0.f, 0.f, 0.f);
    for (int base = 0; base < n; base += 256) {
        const int c = min(256, n - base);
        __syncthreads();
        for (int t = tid; t < c; t += 128) {
            sidx[t] = ri[base + t];
            sp[t]   = rp[base + t];
        }
        __syncthreads();
        int e = 0;
        for (; e + 2 <= c; e += 2) {
            const float p0 = sp[e], p1 = sp[e + 1];
            const uint2 r0 = *(const uint2*)(v1h + (size_t)sidx[e]     * NOUT + tid * 4);
            const uint2 r1 = *(const uint2*)(v1h + (size_t)sidx[e + 1] * NOUT + tid * 4);
            const float2 a0 = __half22float2(*(__half2*)&r0.x);
            const float2 b0 = __half22float2(*(__half2*)&r0.y);
            const float2 a1 = __half22float2(*(__half2*)&r1.x);
            const float2 b1 = __half22float2(*(__half2*)&r1.y);
            acc.x += p0 * a0.x + p1 * a1.x;
            acc.y += p0 * a0.y + p1 * a1.y;
            acc.z += p0 * b0.x + p1 * b1.x;
            acc.w += p0 * b0.y + p1 * b1.y;
        }
        if (e < c) {
            const float p = sp[e];
            const uint2 r0 = *(const uint2*)(v1h + (size_t)sidx[e] * NOUT + tid * 4);
            const float2 a0 = __half22float2(*(__half2*)&r0.x);
            const float2 b0 = __half22float2(*(__half2*)&r0.y);
            acc.x += p * a0.x; acc.y += p * a0.y;
            acc.z += p * b0.x; acc.w += p * b0.y;
        }
    }
    *(float4*)(out + (size_t)m * NOUT + tid * 4) =
        make_float4(0.5f * acc.x, 0.5f * acc.y, 0.5f * acc.z, 0.5f * acc.w);
}

// ---------------------------------------------------------------------------
// Time-path column scan (shuffle-based): prefix sums of v and j*v in fp64.
// ---------------------------------------------------------------------------
__global__ void __launch_bounds__(256)
time_scan_kernel(const float* __restrict__ v2T,
                 float* __restrict__ Pp, float* __restrict__ Qp,
                 float* __restrict__ Ptot, float* __restrict__ Qtot)
{
    __shared__ double wp[8], wq[8];
    __shared__ double carry[2];
    const int c    = blockIdx.x;
    const int tid  = threadIdx.x;
    const int lane = tid & 31, wid = tid >> 5;
    const float* v = v2T + (size_t)c * NR;

    if (tid == 0) { carry[0] = 0.0; carry[1] = 0.0; }
    __syncthreads();

    for (int chunk = 0; chunk < NR / 256; ++chunk) {
        const int rowi = chunk * 256 + tid;
        double p = (double)v[rowi];
        double q = (double)rowi * p;
#pragma unroll
        for (int off = 1; off < 32; off <<= 1) {
            double tp = __shfl_up_sync(0xFFFFFFFFu, p, off);
            double tq = __shfl_up_sync(0xFFFFFFFFu, q, off);
            if (lane >= off) { p += tp; q += tq; }
        }
        if (lane == 31) { wp[wid] = p; wq[wid] = q; }
        __syncthreads();
        if (wid == 0) {
            double a = (lane < 8) ? wp[lane] : 0.0;
            double b = (lane < 8) ? wq[lane] : 0.0;
#pragma unroll
            for (int off = 1; off < 8; off <<= 1) {
                double ta = __shfl_up_sync(0xFFFFFFFFu, a, off);
                double tb = __shfl_up_sync(0xFFFFFFFFu, b, off);
                if (lane >= off) { a += ta; b += tb; }
            }
            if (lane < 8) { wp[lane] = a; wq[lane] = b; }
        }
        __syncthreads();
        p += carry[0] + (wid ? wp[wid - 1] : 0.0);
        q += carry[1] + (wid ? wq[wid - 1] : 0.0);
        Pp[(size_t)c * NR + rowi] = (float)p;
        Qp[(size_t)c * NR + rowi] = (float)q;
        __syncthreads();
        if (tid == 255) {
            carry[0] = p; carry[1] = q;
            if (chunk == NR / 256 - 1) { Ptot[c] = (float)p; Qtot[c] = (float)q; }
        }
    }
}

// ---------------------------------------------------------------------------
// Time-path add: out[m,c] += 0.5*time(m,c).  tp[i][tx] = Pp[c0+i][m0+tx];
// value for (m=m0+i, c=c0+tx) is tp[tx][i].
// ---------------------------------------------------------------------------
__global__ void __launch_bounds__(256)
time_add_kernel(float* __restrict__ out,
                const float* __restrict__ Pp, const float* __restrict__ Qp,
                const float* __restrict__ Ptot, const float* __restrict__ Qtot)
{
    __shared__ float tp[32][33], tq[32][33];
    const int tx = threadIdx.x;
    const int ty = threadIdx.y;
    const int c0 = blockIdx.x * 32;
    const int m0 = blockIdx.y * 32;

#pragma unroll
    for (int i = ty; i < 32; i += 8) {
        tp[i][tx] = Pp[(size_t)(c0 + i) * NR + m0 + tx];
        tq[i][tx] = Qp[(size_t)(c0 + i) * NR + m0 + tx];
    }
    __syncthreads();

#pragma unroll
    for (int i = ty; i < 32; i += 8) {
        const int m = m0 + i;
        const int c = c0 + tx;
        const long long ir = (long long)m;
        const long long s1 = ir * (ir + 1) / 2;
        const long long s2 = (long long)(NR - 1 - ir) * (NR - ir) / 2;
        const float inv_rs = 1.0f / (float)((long long)NR * NR - s1 - s2);
        const float fi = (float)m;
        const float numer = ((float)NR + fi) * Ptot[c] - Qtot[c]
                          - 2.0f * fi * tp[tx][i] + 2.0f * tq[tx][i];
        out[(size_t)m * NOUT + c] += 0.5f * numer * inv_rs;
    }
}

// ---------------------------------------------------------------------------
extern "C" void kernel_launch(void* const* d_in, const int* in_sizes, int n_in,
                              void* d_out, int out_size)
{
    const float* x  = (const float*)d_in[0];
    const float* W0 = (const float*)d_in[1];
    const float* W1 = (const float*)d_in[2];
    const float* w  = (const float*)d_in[3];
    const float* wt = (const float*)d_in[4];
    float* out = (float*)d_out;

    cudaFuncSetAttribute(gemmH<4, 3>, cudaFuncAttributeMaxDynamicSharedMemorySize, 3 * 40960);
    cudaFuncSetAttribute(gemmH<3, 3>, cudaFuncAttributeMaxDynamicSharedMemorySize, 3 * 40960);
    cudaFuncSetAttribute(gemmH<0, 1>, cudaFuncAttributeMaxDynamicSharedMemorySize, 3 * 20480);
    cudaFuncSetAttribute(gemmH<3, 1>, cudaFuncAttributeMaxDynamicSharedMemorySize, 3 * 20480);

    h16 *xh, *xl, *Wqkh, *Wqkl, *wTh, *wTl, *wtTh, *wtTl, *qkh, *v1h, *Sh;
    float *qkf, *v2T, *Pp, *Qp, *Ptot, *Qtot, *pv;
    uint16_t* idx;
    int* cnt;
    cudaGetSymbolAddress((void**)&xh, g_xh);     cudaGetSymbolAddress((void**)&xl, g_xl);
    cudaGetSymbolAddress((void**)&Wqkh, g_Wqkh); cudaGetSymbolAddress((void**)&Wqkl, g_Wqkl);
    cudaGetSymbolAddress((void**)&wTh, g_wTh);   cudaGetSymbolAddress((void**)&wTl, g_wTl);
    cudaGetSymbolAddress((void**)&wtTh, g_wtTh); cudaGetSymbolAddress((void**)&wtTl, g_wtTl);
    cudaGetSymbolAddress((void**)&qkf, g_qkf);   cudaGetSymbolAddress((void**)&qkh, g_qkh);
    cudaGetSymbolAddress((void**)&v1h, g_v1h);
    cudaGetSymbolAddress((void**)&v2T, g_v2T);
    cudaGetSymbolAddress((void**)&Sh, g_Sh);
    cudaGetSymbolAddress((void**)&Pp, g_Pp);     cudaGetSymbolAddress((void**)&Qp, g_Qp);
    cudaGetSymbolAddress((void**)&Ptot, g_Ptot); cudaGetSymbolAddress((void**)&Qtot, g_Qtot);
    cudaGetSymbolAddress((void**)&idx, g_idx);
    cudaGetSymbolAddress((void**)&pv, g_pv);
    cudaGetSymbolAddress((void**)&cnt, g_cnt);

    // input splits
    split_kernel<<<2048, 256>>>(x, xh, xl, NR * INSZ);
    split_kernel<<<256, 256>>>(W0, Wqkh, Wqkl, FEAT * INSZ);
    split_kernel<<<256, 256>>>(W1, Wqkh + FEAT * INSZ, Wqkl + FEAT * INSZ, FEAT * INSZ);
    tsplit_kernel<<<(INSZ * NOUT + 255) / 256, 256>>>(w, wTh, wTl);
    tsplit_kernel<<<(INSZ * NOUT + 255) / 256, 256>>>(wt, wtTh, wtTl);

    // q|k = x @ [W0;W1]^T -> fp32 + fp16 [8192, 256]
    gemmH<4, 3><<<dim3(2, NR / 128), 256, 3 * 40960>>>(
        xh, xl, INSZ, Wqkh, Wqkl, INSZ, qkf, qkh, 256, INSZ);

    // v1 = x @ w -> fp16 [8192, 512]
    gemmH<3, 3><<<dim3(NOUT / 128, NR / 128), 256, 3 * 40960>>>(
        xh, xl, INSZ, wTh, wTl, INSZ, nullptr, v1h, NOUT, INSZ);

    // v2T = wt^T @ x^T -> fp32 [512, 8192]  (single-product: time path is 40x diluted)
    gemmH<0, 1><<<dim3(NR / 128, NOUT / 128), 256, 3 * 20480>>>(
        wtTh, nullptr, INSZ, xh, nullptr, INSZ, v2T, nullptr, NR, INSZ);

    // time-path prefix sums + totals
    time_scan_kernel<<<NOUT, 256>>>(v2T, Pp, Qp, Ptot, Qtot);

    // screening S = q @ k^T -> fp16 [8192, 8192]  (single product)
    gemmH<3, 1><<<dim3(NR / 128, NR / 128), 256, 3 * 20480>>>(
        qkh, nullptr, 256, qkh + 128, nullptr, 256, nullptr, Sh, NR, FEAT);

    // screening softmax + exact recompute + compaction
    softmax_compact2<<<NR, 256>>>(Sh, qkf, idx, pv, cnt);

    // out = 0.5 * (P_sparse @ v1)
    spmm_h<<<NR, 128>>>(idx, pv, cnt, v1h, out);

    // out += 0.5 * time-path
    time_add_kernel<<<dim3(NOUT / 32, NR / 32), dim3(32, 8)>>>(out, Pp, Qp, Ptot, Qtot);
}